// round 4
// baseline (speedup 1.0000x reference)
#include <cuda_runtime.h>
#include <cuda_fp16.h>
#include <stdint.h>

// GraphMatcher power iteration, GB300/sm_100a.
// K stored once as u8 = round(255*K^2) (squared domain doubles precision at the
// large-K winners; sqrt per message restores). Per-graph CTA stages 176 of 288
// edges' K rows in SMEM once and reuses them across all 20 iterations; the
// remaining 112 edges stream from L2 with depth-2 register prefetch.
// Inner loop is fp16x2 SIMD: PRMT builds half2(1024+v), HFMA2 cancels the 1024,
// HMAX2 reduces.

#define BSZ      128
#define NV       32
#define EPG      256
#define EDGES_G  (EPG + NV)          // 288
#define E_RAND   (BSZ * EPG)         // 32768
#define E_TOT    (E_RAND + BSZ * NV) // 36864
#define NN       (NV * NV)           // 1024
#define ITERS    20
#define THREADS  512
#define WARPS    16
#define NSTAGE   176                 // staged edges (11 per warp)
#define NSTREAM  (EDGES_G - NSTAGE)  // 112 streamed (7 per warp)

// 37.75 MB u8 scratch for quantized K^2
__device__ uint8_t g_K8[(size_t)E_TOT * NN];

// ---------------------------------------------------------------------------
// Quantize K (fp32 in [0,1)) -> u8 fixed point of K^2. 16 elements per thread.
// ---------------------------------------------------------------------------
__global__ void k_convert(const float* __restrict__ K) {
    size_t i = ((size_t)blockIdx.x * blockDim.x + threadIdx.x) * 16;
    if (i >= (size_t)E_TOT * NN) return;
    uint32_t w[4];
    #pragma unroll
    for (int q = 0; q < 4; q++) {
        const float4 a = *(const float4*)(K + i + q * 4);
        uint32_t b0 = __float2uint_rn(a.x * a.x * 255.f);
        uint32_t b1 = __float2uint_rn(a.y * a.y * 255.f);
        uint32_t b2 = __float2uint_rn(a.z * a.z * 255.f);
        uint32_t b3 = __float2uint_rn(a.w * a.w * 255.f);
        w[q] = b0 | (b1 << 8) | (b2 << 16) | (b3 << 24);
    }
    *(uint4*)(g_K8 + i) = make_uint4(w[0], w[1], w[2], w[3]);
}

// ---------------------------------------------------------------------------
// Block-wide sum over 512 threads.
// ---------------------------------------------------------------------------
__device__ __forceinline__ float block_sum512(float v, float* red, int tid) {
    #pragma unroll
    for (int o = 16; o > 0; o >>= 1) v += __shfl_down_sync(0xFFFFFFFFu, v, o);
    if ((tid & 31) == 0) red[tid >> 5] = v;
    __syncthreads();
    if (tid < 32) {
        float w = (tid < WARPS) ? red[tid] : 0.f;
        #pragma unroll
        for (int o = 8; o > 0; o >>= 1) w += __shfl_down_sync(0xFFFFFFFFu, w, o);
        if (tid == 0) red[0] = w;
    }
    __syncthreads();
    float r = red[0];
    __syncthreads();
    return r;
}

// 4 u8 K-values vs one uint4 of packed x^2 data (X01,Y01,X23,Y23 as half2 bits).
// h = 1024+v exactly (bits 0x6400|v); hfma2(h, X, -1024*X) = v*X, one rounding.
__device__ __forceinline__ void quad_op(uint32_t kw, uint4 xv,
                                        __half2& ma, __half2& mb) {
    uint32_t h01u = __byte_perm(kw, 0x64646464u, 0x4140);
    uint32_t h23u = __byte_perm(kw, 0x64646464u, 0x4342);
    __half2 h01 = *reinterpret_cast<__half2*>(&h01u);
    __half2 h23 = *reinterpret_cast<__half2*>(&h23u);
    __half2 X01 = *reinterpret_cast<__half2*>(&xv.x);
    __half2 Y01 = *reinterpret_cast<__half2*>(&xv.y);
    __half2 X23 = *reinterpret_cast<__half2*>(&xv.z);
    __half2 Y23 = *reinterpret_cast<__half2*>(&xv.w);
    ma = __hmax2(ma, __hfma2(h01, X01, Y01));
    mb = __hmax2(mb, __hfma2(h23, X23, Y23));
}

// Compute one edge's messages from its two K quad-words and write to msgs.
__device__ __forceinline__ void edge_compute(int k, uint4 q0, uint4 q1,
                                             const uint4* __restrict__ xq,
                                             const uint16_t* __restrict__ edst,
                                             float* __restrict__ msgs, int lane) {
    const uint4* xd = xq + (int)edst[k] * 8;
    __half2 ma = __float2half2_rn(0.f), mb = ma;
    quad_op(q0.x, xd[0], ma, mb);
    quad_op(q0.y, xd[1], ma, mb);
    quad_op(q0.z, xd[2], ma, mb);
    quad_op(q0.w, xd[3], ma, mb);
    quad_op(q1.x, xd[4], ma, mb);
    quad_op(q1.y, xd[5], ma, mb);
    quad_op(q1.z, xd[6], ma, mb);
    quad_op(q1.w, xd[7], ma, mb);
    __half2 m2 = __hmax2(ma, mb);
    float m2f = __half2float(__hmax(__low2half(m2), __high2half(m2)));
    float msg;
    asm("sqrt.approx.f32 %0, %1;" : "=f"(msg) : "f"(m2f));
    msgs[k * NV + lane] = msg;
}

// ---------------------------------------------------------------------------
// SMEM layout (bytes):
//   smK    [0      .. 180224)  staged K rows for edges 0..175 (176 KB)
//   msgs   [180224 .. 217088)  288*32 fp32
//   xq     [217088 .. 221184)  32 nodes * 8 quad-uint4 (packed x^2 half2)
//   outv   [221184 .. 225280)  1024 fp32 (unnormalized x)
//   eglobS [225280 .. 225728)  112 int   (global rows for streamed edges)
//   esrc   [225728 .. 226304)  288 u16
//   edst   [226304 .. 226880)  288 u16
//   glist  [226880 .. 227456)  288 u16
//   goff   [227456 .. 227588)  33 int
//   red    [227588 .. 227716)  32 fp32
// ---------------------------------------------------------------------------
#define SMEM_BYTES 227716

__global__ __launch_bounds__(THREADS, 1) void k_mpm(
    const void* __restrict__ ei_raw,
    const float* __restrict__ x_in,
    float* __restrict__ out)
{
    extern __shared__ char sm[];
    uint8_t*  smK    = (uint8_t*)sm;
    float*    msgs   = (float*)(sm + 180224);
    uint4*    xq     = (uint4*)(sm + 217088);
    float*    outv   = (float*)(sm + 221184);
    int*      eglobS = (int*)(sm + 225280);
    uint16_t* esrc   = (uint16_t*)(sm + 225728);
    uint16_t* edst   = (uint16_t*)(sm + 226304);
    uint16_t* glist  = (uint16_t*)(sm + 226880);
    int*      goff   = (int*)(sm + 227456);
    float*    red    = (float*)(sm + 227588);

    const int tid  = threadIdx.x;
    const int g    = blockIdx.x;
    const int wid  = tid >> 5, lane = tid & 31;

    // ---- int32/int64 detection (warp 0, broadcast through red[1]) ----
    if (tid < 32) {
        unsigned long long v = ((const unsigned long long*)ei_raw)[1 + (lane & 15)];
        unsigned bal = __ballot_sync(0xFFFFFFFFu, v < 4096ull);
        if (lane == 0) red[1] = (bal == 0xFFFFFFFFu) ? 1.0f : 0.0f;
    }
    __syncthreads();
    const int is64 = (red[1] != 0.0f);

    // ---- per-graph edge tables (edge blocks are contiguous per graph) ----
    for (int k = tid; k < EDGES_G; k += THREADS) {
        int e = (k < EPG) ? (g * EPG + k) : (E_RAND + g * NV + (k - EPG));
        if (k >= NSTAGE) eglobS[k - NSTAGE] = e;
        long long s, d;
        if (is64) {
            const long long* p = (const long long*)ei_raw;
            s = p[e]; d = p[E_TOT + e];
        } else {
            const int* p = (const int*)ei_raw;
            s = p[e]; d = p[E_TOT + e];
        }
        esrc[k] = (uint16_t)(s - (long long)g * NV);
        edst[k] = (uint16_t)(d - (long long)g * NV);
    }
    __syncthreads();

    // per-src gather lists (serial on thread 0; once per launch, tiny)
    if (tid == 0) {
        int cnt[NV];
        #pragma unroll
        for (int s = 0; s < NV; s++) cnt[s] = 0;
        for (int k = 0; k < EDGES_G; k++) cnt[esrc[k]]++;
        int off = 0;
        for (int s = 0; s < NV; s++) { goff[s] = off; off += cnt[s]; cnt[s] = goff[s]; }
        goff[NV] = off;
        for (int k = 0; k < EDGES_G; k++) { int s = esrc[k]; glist[cnt[s]++] = (uint16_t)k; }
    }

    // ---- stage K for edges 0..175 (contiguous rows g*EPG .. g*EPG+175) ----
    {
        const uint4* gp = (const uint4*)(g_K8 + (size_t)g * EPG * NN);
        uint4* sp = (uint4*)smK;
        #pragma unroll
        for (int i = 0; i < (NSTAGE * NN / 16) / THREADS; i++)   // 22 per thread
            sp[tid + i * THREADS] = gp[tid + i * THREADS];
    }

    // ---- x0: load raw x, get norm ----
    float ss = 0.f;
    for (int t = tid; t < NN; t += THREADS) {
        float v = x_in[(size_t)g * NN + t];
        outv[t] = v;
        ss += v * v;
    }
    float inv = rsqrtf(block_sum512(ss, red, tid));

    const __half2 NEG1024 = __float2half2_rn(-1024.f);

    for (int it = 0; it < ITERS; it++) {
        // ---- pack x^2 as half2 quads: xq[node*8+q] = (X01,Y01,X23,Y23) ----
        if (tid < NV * 8) {
            int node = tid >> 3, q = tid & 7, j0 = q * 4;
            const float* xr = outv + node * NV + j0;
            float v0 = xr[0] * inv, v1 = xr[1] * inv, v2 = xr[2] * inv, v3 = xr[3] * inv;
            __half2 Xa = __floats2half2_rn(v0 * v0, v1 * v1);
            __half2 Xb = __floats2half2_rn(v2 * v2, v3 * v3);
            __half2 Ya = __hmul2(Xa, NEG1024);   // exact (power of two)
            __half2 Yb = __hmul2(Xb, NEG1024);
            uint4 w;
            w.x = *reinterpret_cast<uint32_t*>(&Xa);
            w.y = *reinterpret_cast<uint32_t*>(&Ya);
            w.z = *reinterpret_cast<uint32_t*>(&Xb);
            w.w = *reinterpret_cast<uint32_t*>(&Yb);
            xq[tid] = w;
        }
        __syncthreads();

        // ---- phase 1: per-edge messages. warp<->edge, lane<->row i ----
        // msg[e][i] = sqrt(max_j x2[dst][j] * K2[e][i][j])   (scale-free)

        // hoist first two streamed prefetches (covered by staged compute)
        uint4 b0[2], b1[2];
        {
            const uint4* p0 = (const uint4*)(g_K8 + (size_t)eglobS[wid] * NN) + lane * 2;
            b0[0] = p0[0]; b0[1] = p0[1];
            const uint4* p1 = (const uint4*)(g_K8 + (size_t)eglobS[wid + WARPS] * NN) + lane * 2;
            b1[0] = p1[0]; b1[1] = p1[1];
        }

        // staged edges: 11 per warp, K from SMEM
        #pragma unroll
        for (int s = 0; s < NSTAGE / WARPS; s++) {
            int k = wid + s * WARPS;
            const uint4* p = (const uint4*)(smK + k * NN) + lane * 2;
            uint4 q0 = p[0], q1 = p[1];
            edge_compute(k, q0, q1, xq, edst, msgs, lane);
        }

        // streamed edges: 7 per warp, depth-2 register prefetch
        #pragma unroll
        for (int s = 0; s < NSTREAM / WARPS; s++) {
            int k = NSTAGE + wid + s * WARPS;
            uint4 q0, q1;
            if (s & 1) { q0 = b1[0]; q1 = b1[1]; }
            else       { q0 = b0[0]; q1 = b0[1]; }
            if (s + 2 < NSTREAM / WARPS) {
                int idx = wid + (s + 2) * WARPS;
                const uint4* pn = (const uint4*)(g_K8 + (size_t)eglobS[idx] * NN) + lane * 2;
                if (s & 1) { b1[0] = pn[0]; b1[1] = pn[1]; }
                else       { b0[0] = pn[0]; b0[1] = pn[1]; }
            }
            edge_compute(k, q0, q1, xq, edst, msgs, lane);
        }
        __syncthreads();

        // ---- phase 2: segment-sum over src + squared-norm partial ----
        float ss2 = 0.f;
        for (int t = tid; t < NN; t += THREADS) {
            int s = t >> 5, i = t & 31;      // warp-uniform s -> broadcast list loads
            float a = 0.f;
            int b = goff[s], e2 = goff[s + 1];
            for (int q = b; q < e2; q++)
                a += msgs[(int)glist[q] * NV + i];
            outv[t] = a;
            ss2 += a * a;
        }
        inv = rsqrtf(block_sum512(ss2, red, tid));
        // outv stays unnormalized; inv carried in registers
    }

    // ---- output: out[g, i, s] = x[g*32+s, i]  (transpose last two dims) ----
    for (int t = tid; t < NN; t += THREADS) {
        int i = t >> 5, s = t & 31;
        out[(size_t)g * NN + t] = outv[s * NV + i] * inv;
    }
}

// ---------------------------------------------------------------------------
extern "C" void kernel_launch(void* const* d_in, const int* in_sizes, int n_in,
                              void* d_out, int out_size) {
    const float* K  = (const float*)d_in[0];
    const void*  ei = d_in[1];
    const float* x  = (const float*)d_in[2];
    float* out = (float*)d_out;

    (void)in_sizes; (void)n_in; (void)out_size;

    cudaFuncSetAttribute(k_mpm, cudaFuncAttributeMaxDynamicSharedMemorySize, SMEM_BYTES);

    // 36864*1024 elems / 16 per thread / 256 per block = 9216 blocks (exact)
    k_convert<<<9216, 256>>>(K);

    k_mpm<<<BSZ, THREADS, SMEM_BYTES>>>(ei, x, out);
}